// round 8
// baseline (speedup 1.0000x reference)
#include <cuda_runtime.h>
#include <cstdint>

#define KDIM 64
#define MDIM 16
#define TPB  256
#define NPAIR 4                   // warp pairs per block
#define IROWS 32                  // rows per work item
#define KC   32                   // k per chunk (2 chunks per item)
#define TSTRIDE 36                // floats per tile row (32 data + 4 pad)
#define SLICE (IROWS * TSTRIDE)   // 1152 floats per buffer

typedef unsigned long long u64;
typedef unsigned int u32;

__device__ __forceinline__ u64 pack2(float lo, float hi) {
    u64 r;
    asm("mov.b64 %0, {%1, %2};" : "=l"(r) : "f"(lo), "f"(hi));
    return r;
}
__device__ __forceinline__ void unpack2(u64 v, float& lo, float& hi) {
    asm("mov.b64 {%0, %1}, %2;" : "=f"(lo), "=f"(hi) : "l"(v));
}
__device__ __forceinline__ u64 fma2(u64 a, u64 b, u64 c) {
    u64 d;
    asm("fma.rn.f32x2 %0, %1, %2, %3;" : "=l"(d) : "l"(a), "l"(b), "l"(c));
    return d;
}
__device__ __forceinline__ void cp16(u32 smem_dst, const void* gsrc) {
    asm volatile("cp.async.cg.shared.global [%0], [%1], 16;\n"
                 :: "r"(smem_dst), "l"(gsrc));
}
__device__ __forceinline__ void cp_commit() {
    asm volatile("cp.async.commit_group;\n");
}
template <int N>
__device__ __forceinline__ void cp_wait() {
    asm volatile("cp.async.wait_group %0;\n" :: "n"(N));
}
__device__ __forceinline__ void pair_bar(int id) {
    asm volatile("bar.sync %0, 64;" :: "r"(id) : "memory");
}

__global__ __launch_bounds__(TPB, 4)
void dual_compress_kernel(const float* __restrict__ phi_fwd,
                          const float* __restrict__ phi_bwd,
                          const float* __restrict__ alpha_fwd,
                          const float* __restrict__ alpha_bwd,
                          float* __restrict__ out,
                          int V)
{
    // Per-pair double buffers: 4 x 2 x 1152 floats = 36,864 B
    __shared__ float tile[NPAIR][2][SLICE];
    // Both sides' weight tables: swq[side][k*4 + j] packs m-pairs {2j..2j+3}
    __shared__ ulonglong2 swq[2 * KDIM * 4];   // 8,192 B
    u64* swf = (u64*)swq;

    const int tid  = threadIdx.x;
    const int w    = tid >> 5;
    const int lane = tid & 31;
    const int p    = w & 3;          // pair id (tile owner)
    const int h    = w >> 2;         // m-half: 0 -> m[0:8), 1 -> m[8:16)
    const int wtid = lane + 32 * h;  // 0..63 within pair

    const int V32 = (V + IROWS - 1) / IROWS;   // items per side
    const int NIT = 2 * V32;                   // total items
    const int NP  = gridDim.x * NPAIR;         // total pairs on chip
    const int g   = blockIdx.x * NPAIR + p;    // this pair's global id

    const int nmy = (g < NIT) ? (NIT - 1 - g) / NP + 1 : 0;
    const int nch = 2 * nmy;                   // chunks to process

    u32 tb0 = (u32)__cvta_generic_to_shared(&tile[p][0][0]);
    u32 tb1 = (u32)__cvta_generic_to_shared(&tile[p][1][0]);

    // --- staging helper (inlined twice below): stage chunk index n into buffer n&1
    auto stage = [&](int n) {
        const int it   = g + (n >> 1) * NP;
        const int side = (it >= V32) ? 1 : 0;
        const int rb   = (it - side * V32) * IROWS;
        const int ck   = n & 1;
        const float* __restrict__ phi = side ? phi_bwd : phi_fwd;
        const u32 tb = (n & 1) ? tb1 : tb0;
        // 32 rows x 32 floats = 256 float4; 64 threads -> 4 each
#pragma unroll
        for (int i = 0; i < 4; ++i) {
            int idx  = wtid + i * 64;
            int row  = idx >> 3;                 // 0..31
            int c4   = idx & 7;
            int grow = min(rb + row, V - 1);
            cp16(tb + (u32)(row * TSTRIDE + c4 * 4) * 4u,
                 phi + (size_t)grow * KDIM + ck * KC + c4 * 4);
        }
        cp_commit();
    };

    // --- prologue: stage first two chunks
    if (nch > 0) stage(0);
    if (nch > 1) stage(1);

    // --- build both weight tables: swf[side*512 + k*8 + mp]
#pragma unroll
    for (int t = 0; t < 4; ++t) {
        int idx  = tid + t * TPB;               // 0..1023
        int side = idx >> 9;
        int rem  = idx & 511;
        int k    = rem >> 3;
        int mp   = rem & 7;
        const float* __restrict__ alpha = side ? alpha_bwd : alpha_fwd;
        float w0 = __expf(alpha[(2 * mp)     * KDIM + k]);
        float w1 = __expf(alpha[(2 * mp + 1) * KDIM + k]);
        swf[idx] = pack2(w0, w1);
    }
    __syncthreads();   // weights visible; only CTA-wide barrier

    u64 acc[4];
#pragma unroll
    for (int q = 0; q < 4; ++q) acc[q] = 0ull;

    for (int n = 0; n < nch; ++n) {
        if (n == nch - 1) cp_wait<0>(); else cp_wait<1>();
        pair_bar(1 + p);   // both warps' data for this chunk landed

        const int it   = g + (n >> 1) * NP;
        const int side = (it >= V32) ? 1 : 0;
        const int rb   = (it - side * V32) * IROWS;
        const int buf  = n & 1;
        const int ck   = n & 1;

        const float4* __restrict__ t4 =
            (const float4*)&tile[p][buf][lane * TSTRIDE];
        const ulonglong2* __restrict__ wt = &swq[side * KDIM * 4];

#pragma unroll
        for (int j4 = 0; j4 < KC / 4; ++j4) {             // 8 iters
            float4 a = t4[j4];
            float e0 = __expf(a.x), e1 = __expf(a.y),
                  e2 = __expf(a.z), e3 = __expf(a.w);
            const int kbase = ck * KC + j4 * 4;

#pragma unroll
            for (int j = 0; j < 4; ++j) {
                const int k = kbase + j;
                float ej = (j == 0) ? e0 : (j == 1) ? e1 : (j == 2) ? e2 : e3;
                u64 E = pack2(ej, ej);
                ulonglong2 wA = wt[k * 4 + 2 * h + 0];
                ulonglong2 wB = wt[k * 4 + 2 * h + 1];
                acc[0] = fma2(E, wA.x, acc[0]);
                acc[1] = fma2(E, wA.y, acc[1]);
                acc[2] = fma2(E, wB.x, acc[2]);
                acc[3] = fma2(E, wB.y, acc[3]);
            }
        }

        // prefetch chunk n+2 into the buffer we just consumed
        if (n + 2 < nch) {
            pair_bar(1 + p);   // both warps done reading tile[p][buf]
            stage(n + 2);
        }

        // item boundary: finalize and store
        if (n & 1) {
            float yv[8];
#pragma unroll
            for (int q = 0; q < 4; ++q) {
                float sa, sb;
                unpack2(acc[q], sa, sb);
                yv[2 * q]     = __logf(sa);
                yv[2 * q + 1] = __logf(sb);
                acc[q] = 0ull;
            }
            const int r = rb + lane;
            if (r < V) {
                float* yside = out + (size_t)side * (size_t)V * MDIM;
                float4* o = (float4*)(yside + (size_t)r * MDIM + 8 * h);
                o[0] = make_float4(yv[0], yv[1], yv[2], yv[3]);
                o[1] = make_float4(yv[4], yv[5], yv[6], yv[7]);
            }
        }
    }
}

extern "C" void kernel_launch(void* const* d_in, const int* in_sizes, int n_in,
                              void* d_out, int out_size)
{
    const float* d_out_t   = (const float*)d_in[0];  // (V, 64) fwd phi
    const float* d_in_t    = (const float*)d_in[1];  // (V, 64) bwd phi
    const float* alpha_fwd = (const float*)d_in[2];  // (16, 64)
    const float* alpha_bwd = (const float*)d_in[3];  // (16, 64)
    float* out = (float*)d_out;                      // [y_fwd (V,16) | y_bwd (V,16)]

    const int V = in_sizes[0] / KDIM;

    // One exact wave: 148 SMs x 4 blocks/SM
    dual_compress_kernel<<<592, TPB>>>(d_out_t, d_in_t, alpha_fwd, alpha_bwd, out, V);
}